// round 8
// baseline (speedup 1.0000x reference)
#include <cuda_runtime.h>
#include <cstdint>

#define CC   128
#define HH   56
#define NB   64
#define HW   3136
#define PW   58
#define PPI  (PW*PW)             // 3364
#define PTOT (NB*PPI)            // 215296
#define NTIL (PTOT/128)          // 1682
#define GUARD 64
#define NPX  (NB*HW)             // 200704

// ---------------- device scratch (zero-init at load; halo/guards never written) ----
__device__ unsigned g_alphaBits[2];
__device__ double   g_red[2][2][CC];
__device__ float    g_coef[2][2][CC];
__device__ __align__(128) signed char g_act8[(size_t)(PTOT + 2*GUARD) * CC]; // NHWC padded, k in 0..15
__device__ __align__(128) signed char g_wp8[2][9 * 128 * 128];               // [tap][oc][ci], m in -7..7
__device__ float    g_y[(size_t)PTOT * CC];                                   // S, NHWC f32 (exact ints)

// ---------------- helpers ----------------
__device__ __forceinline__ uint32_t smem_u32(const void* p) {
    uint32_t a; asm("{ .reg .u64 t; cvta.to.shared.u64 t, %1; cvt.u32.u64 %0, t; }":"=r"(a):"l"(p));
    return a;
}
__device__ __forceinline__ void cp16(uint32_t dst, unsigned long long src) {
    asm volatile("cp.async.cg.shared.global [%0], [%1], 16;"::"r"(dst),"l"(src));
}
#define CP_COMMIT() asm volatile("cp.async.commit_group;":::"memory")
#define CP_WAIT(n)  asm volatile("cp.async.wait_group %0;"::"n"(n):"memory")

__device__ __forceinline__ void mma_s8(int* c, unsigned a0, unsigned a1, unsigned a2, unsigned a3,
                                       unsigned b0, unsigned b1) {
    asm volatile("mma.sync.aligned.m16n8k32.row.col.s32.s8.s8.s32 "
                 "{%0,%1,%2,%3}, {%4,%5,%6,%7}, {%8,%9}, {%0,%1,%2,%3};"
                 : "+r"(c[0]), "+r"(c[1]), "+r"(c[2]), "+r"(c[3])
                 : "r"(a0), "r"(a1), "r"(a2), "r"(a3), "r"(b0), "r"(b1));
}
#define LDSM4(r0,r1,r2,r3,addr) \
    asm volatile("ldmatrix.sync.aligned.m8n8.x4.shared.b16 {%0,%1,%2,%3}, [%4];" \
                 : "=r"(r0),"=r"(r1),"=r"(r2),"=r"(r3) : "r"(addr))
__device__ __forceinline__ uint4 lds128(uint32_t a) {
    uint4 v;
    asm volatile("ld.shared.v4.u32 {%0,%1,%2,%3}, [%4];"
                 : "=r"(v.x),"=r"(v.y),"=r"(v.z),"=r"(v.w) : "r"(a));
    return v;
}

// ---------------- small kernels ----------------
__global__ void k_zero() {
    int t = blockIdx.x*blockDim.x + threadIdx.x;
    if (t < 2) g_alphaBits[t] = 0u;
    if (t < 512) ((double*)g_red)[t] = 0.0;
}
__global__ void k_alpha(const float* __restrict__ w1, const float* __restrict__ w2) {
    const float* w = blockIdx.y ? w2 : w1;
    float m = 0.f;
    for (int i = blockIdx.x*blockDim.x + threadIdx.x; i < CC*CC*9; i += gridDim.x*blockDim.x)
        m = fmaxf(m, fabsf(w[i]));
    #pragma unroll
    for (int o = 16; o; o >>= 1) m = fmaxf(m, __shfl_xor_sync(~0u, m, o));
    __shared__ float sm[8];
    if ((threadIdx.x & 31) == 0) sm[threadIdx.x>>5] = m;
    __syncthreads();
    if (threadIdx.x < 32) {
        m = (threadIdx.x < (blockDim.x>>5)) ? sm[threadIdx.x] : 0.f;
        #pragma unroll
        for (int o = 16; o; o >>= 1) m = fmaxf(m, __shfl_xor_sync(~0u, m, o));
        if (threadIdx.x == 0) atomicMax(&g_alphaBits[blockIdx.y], __float_as_uint(m));
    }
}
// fused: blocks [0,1152): weight quant; blocks [1152,4288): activation quant
__global__ void k_prep(const float* __restrict__ w1, const float* __restrict__ w2,
                       const float* __restrict__ x) {
    int b = blockIdx.x, tid = threadIdx.x;
    if (b < 1152) {
        int conv = b / 576;
        const float* w = conv ? w2 : w1;
        float alpha = __uint_as_float(g_alphaBits[conv]);
        int idx = (b % 576)*256 + tid;
        if (idx < 9*128*128) {
            int tap = idx >> 14, rem = idx & 16383, oc = rem >> 7, ci = rem & 127;
            float wc = fminf(fmaxf(w[((size_t)oc*CC + ci)*9 + tap] / alpha, -1.f), 1.f);
            g_wp8[conv][idx] = (signed char)__float2int_rn(wc * 7.f);
        }
        return;
    }
    __shared__ unsigned ws[32*65];
    int bb = b - 1152;
    int n = bb / 49, hw0 = (bb % 49)*64;
    int c4 = tid >> 3, q = tid & 7;
    const float* xp = x + ((size_t)(n*CC + c4*4))*HW + hw0 + q*8;
    unsigned w[8] = {0,0,0,0,0,0,0,0};
    #pragma unroll
    for (int j = 0; j < 4; j++)
        #pragma unroll
        for (int p = 0; p < 8; p++) {
            float v = xp[(size_t)j*HW + p];
            int k = __float2int_rn(fminf(fmaxf(v, 0.f), 1.f) * 15.f);
            w[p] |= (unsigned)k << (8*j);
        }
    #pragma unroll
    for (int p = 0; p < 8; p++) ws[c4*65 + q*8 + p] = w[p];
    __syncthreads();
    unsigned* A = (unsigned*)(g_act8 + (size_t)GUARD*128);
    int wd = tid & 31;
    #pragma unroll
    for (int pl = tid >> 5; pl < 64; pl += 8) {
        int hw = hw0 + pl;
        size_t p = (size_t)n*PPI + (hw/HH + 1)*PW + (hw%HH) + 1;
        A[p*32 + wd] = ws[wd*65 + pl];
    }
}
// BN(S)+act_quant -> k (0..15) NHWC-padded
__global__ void k_bnq() {
    int idx = blockIdx.x*512 + threadIdx.x;
    int v = idx >> 5, q = idx & 31;
    int n = v / HW, hw = v % HW;
    size_t p = (size_t)n*PPI + (hw/HH + 1)*PW + (hw%HH) + 1;
    float4 sv = ((const float4*)(g_y + p*128))[q];
    int c0 = q*4;
    float f[4] = {sv.x, sv.y, sv.z, sv.w};
    unsigned word = 0;
    #pragma unroll
    for (int j = 0; j < 4; j++) {
        float bn = fmaf(g_coef[0][0][c0+j], f[j], g_coef[0][1][c0+j]);
        int k = __float2int_rn(fminf(fmaxf(bn, 0.f), 1.f) * 15.f);
        word |= (unsigned)k << (8*j);
    }
    *(unsigned*)(g_act8 + (size_t)GUARD*128 + p*128 + c0) = word;
}
__global__ void k_reduce(int slot) {
    __shared__ double sm[2][4][128];
    int c = threadIdx.x & 127, g = threadIdx.x >> 7;
    double s = 0.0, s2 = 0.0;
    int base = blockIdx.x*512;
    for (int j = 0; j < 128; j++) {
        int v = base + j*4 + g;
        int n = v / HW, hw = v % HW;
        size_t p = (size_t)n*PPI + (hw/HH + 1)*PW + (hw%HH) + 1;
        double val = (double)g_y[p*128 + c];
        s += val; s2 += val*val;
    }
    sm[0][g][c] = s; sm[1][g][c] = s2;
    __syncthreads();
    if (threadIdx.x < 128) {
        s  = sm[0][0][c]+sm[0][1][c]+sm[0][2][c]+sm[0][3][c];
        s2 = sm[1][0][c]+sm[1][1][c]+sm[1][2][c]+sm[1][3][c];
        atomicAdd(&g_red[slot][0][c], s);
        atomicAdd(&g_red[slot][1][c], s2);
    }
}
__global__ void k_stats(int slot, const float* __restrict__ gamma, const float* __restrict__ beta) {
    int c = threadIdx.x;
    double scale = (double)__uint_as_float(g_alphaBits[slot]) / 105.0;
    double mean = g_red[slot][0][c] / (double)NPX;
    double var  = g_red[slot][1][c] / (double)NPX - mean*mean;
    double rstd = 1.0 / sqrt(var*scale*scale + 1e-5);
    double g = (double)gamma[c];
    g_coef[slot][0][c] = (float)(g * rstd * scale);
    g_coef[slot][1][c] = (float)((double)beta[c] - g * rstd * mean * scale);
}
__global__ void k_final(const float* __restrict__ x, float* __restrict__ out) {
    __shared__ float sf[128*57];
    int y = blockIdx.x + 1, n = blockIdx.y, tid = threadIdx.x;
    size_t p0 = (size_t)n*PPI + y*PW + 1;
    for (int i = tid; i < 56*128; i += 256) {
        int px = i >> 7, c = i & 127;
        sf[c*57 + px] = g_y[(p0 + px)*128 + c];
    }
    __syncthreads();
    for (int i = tid; i < 128*56; i += 256) {
        int c = i / 56, px = i % 56;
        size_t o = ((size_t)(n*CC + c))*HW + (y-1)*HH + px;
        out[o] = fmaf(g_coef[1][0][c], sf[c*57+px], g_coef[1][1][c]) + x[o];
    }
}

// ---------------- hybrid conv: warps 0-7 IMMA (px 0-63), warps 8-15 dp4a (px 64-127)
#define AROWS 246
#define ASTR  144
#define BSTR  144
#define SM_A  0
#define SM_B  (AROWS*ASTR)                 // 35424
#define SM_SZ (SM_B + 9*128*BSTR)          // 35424 + 165888 = 201312

__global__ void __launch_bounds__(512, 1) k_conv(int conv) {
    extern __shared__ __align__(128) char smem[];
    uint32_t sb = smem_u32(smem);
    int tid = threadIdx.x, wid = tid >> 5, lane = tid & 31;

    unsigned long long Ag = (unsigned long long)__cvta_generic_to_global(g_act8 + (size_t)GUARD*128);
    unsigned long long Bg = (unsigned long long)__cvta_generic_to_global(g_wp8[conv]);

    // stage B once: row stride 144B
    for (int i = tid; i < 9216; i += 512) {
        int tap = i >> 10, r = i & 1023, oc = r >> 3, c = r & 7;
        cp16(sb + SM_B + (tap*128 + oc)*BSTR + (c << 4), Bg + (size_t)i*16);
    }
    CP_COMMIT();

    const int offs[9] = {-59,-58,-57,-1,0,1,57,58,59};

    // IMMA lane geometry
    int lm = lane >> 3, lr = lane & 7;
    uint32_t a_lane = (uint32_t)(((lm & 1)*8 + lr) * ASTR + (lm >> 1)*16);
    int b_oc_row = (lm >> 1)*8 + lr;
    uint32_t b_koff = (uint32_t)(lm & 1) * 16;

    for (long long tile = blockIdx.x; tile < NTIL; tile += gridDim.x) {
        __syncthreads();                     // prior compute done reading A
        {
            unsigned long long src = Ag + (tile*128 - 59) * 128;
            for (int i = tid; i < 1968; i += 512)
                cp16(sb + SM_A + (i>>3)*ASTR + ((i&7)<<4), src + (size_t)i*16);
            CP_COMMIT(); CP_WAIT(0);
        }
        __syncthreads();

        if (wid < 8) {
            // ---------------- IMMA half: px 0-63 ----------------
            int mwarp = wid >> 2, nwarp = wid & 3;
            int pxw = mwarp * 32, ocb = nwarp * 32;
            uint32_t b_base = sb + SM_B + (uint32_t)(ocb + b_oc_row)*BSTR + b_koff;
            int acc[2][4][4];
            #pragma unroll
            for (int mt = 0; mt < 2; mt++)
                #pragma unroll
                for (int nt = 0; nt < 4; nt++)
                    #pragma unroll
                    for (int j = 0; j < 4; j++) acc[mt][nt][j] = 0;

            #pragma unroll
            for (int tap = 0; tap < 9; tap++) {
                uint32_t aTap = sb + SM_A + (uint32_t)(pxw + offs[tap] + 59) * ASTR + a_lane;
                uint32_t bTap = b_base + (uint32_t)tap * (128*BSTR);
                #pragma unroll
                for (int ks = 0; ks < 4; ks++) {
                    unsigned a0[4], a1[4], b[8];
                    LDSM4(a0[0], a0[1], a0[2], a0[3], aTap + ks*32);
                    LDSM4(a1[0], a1[1], a1[2], a1[3], aTap + ks*32 + 16*ASTR);
                    LDSM4(b[0], b[1], b[2], b[3], bTap + ks*32);              // oc 0-15  (nt 0,1)
                    LDSM4(b[4], b[5], b[6], b[7], bTap + ks*32 + 16*BSTR);    // oc 16-31 (nt 2,3)
                    #pragma unroll
                    for (int nt = 0; nt < 4; nt++) {
                        mma_s8(acc[0][nt], a0[0], a0[1], a0[2], a0[3], b[nt*2], b[nt*2+1]);
                        mma_s8(acc[1][nt], a1[0], a1[1], a1[2], a1[3], b[nt*2], b[nt*2+1]);
                    }
                }
            }
            int g = lane >> 2, t = lane & 3;
            #pragma unroll
            for (int mt = 0; mt < 2; mt++) {
                size_t px0 = (size_t)tile*128 + pxw + mt*16 + g;
                #pragma unroll
                for (int nt = 0; nt < 4; nt++) {
                    int oc = ocb + nt*8 + 2*t;
                    *(float2*)(g_y + px0*128 + oc) =
                        make_float2((float)acc[mt][nt][0], (float)acc[mt][nt][1]);
                    *(float2*)(g_y + (px0 + 8)*128 + oc) =
                        make_float2((float)acc[mt][nt][2], (float)acc[mt][nt][3]);
                }
            }
        } else {
            // ---------------- dp4a half: px 64-127 ----------------
            int sub = wid - 8;
            int ocb = (sub & 3) * 32, pxb = 64 + (sub >> 2) * 32;
            int oc = ocb + lane;
            int acc[32];
            #pragma unroll
            for (int p = 0; p < 32; p++) acc[p] = 0;

            #pragma unroll 1
            for (int tap = 0; tap < 9; tap++) {
                uint32_t bAddr = sb + SM_B + (uint32_t)(tap*128 + oc)*BSTR;
                uint4 B0 = lds128(bAddr);       uint4 B1 = lds128(bAddr + 16);
                uint4 B2 = lds128(bAddr + 32);  uint4 B3 = lds128(bAddr + 48);
                uint4 B4 = lds128(bAddr + 64);  uint4 B5 = lds128(bAddr + 80);
                uint4 B6 = lds128(bAddr + 96);  uint4 B7 = lds128(bAddr + 112);
                uint32_t aBase = sb + SM_A + (uint32_t)(pxb + offs[tap] + 59) * ASTR;
                #pragma unroll 2
                for (int p = 0; p < 32; p++) {
                    uint32_t aA = aBase + p*ASTR;
                    int s = acc[p];
                    uint4 a0 = lds128(aA);
                    s = __dp4a((int)a0.x, (int)B0.x, s); s = __dp4a((int)a0.y, (int)B0.y, s);
                    s = __dp4a((int)a0.z, (int)B0.z, s); s = __dp4a((int)a0.w, (int)B0.w, s);
                    uint4 a1 = lds128(aA + 16);
                    s = __dp4a((int)a1.x, (int)B1.x, s); s = __dp4a((int)a1.y, (int)B1.y, s);
                    s = __dp4a((int)a1.z, (int)B1.z, s); s = __dp4a((int)a1.w, (int)B1.w, s);
                    uint4 a2 = lds128(aA + 32);
                    s = __dp4a((int)a2.x, (int)B2.x, s); s = __dp4a((int)a2.y, (int)B2.y, s);
                    s = __dp4a((int)a2.z, (int)B2.z, s); s = __dp4a((int)a2.w, (int)B2.w, s);
                    uint4 a3 = lds128(aA + 48);
                    s = __dp4a((int)a3.x, (int)B3.x, s); s = __dp4a((int)a3.y, (int)B3.y, s);
                    s = __dp4a((int)a3.z, (int)B3.z, s); s = __dp4a((int)a3.w, (int)B3.w, s);
                    uint4 a4 = lds128(aA + 64);
                    s = __dp4a((int)a4.x, (int)B4.x, s); s = __dp4a((int)a4.y, (int)B4.y, s);
                    s = __dp4a((int)a4.z, (int)B4.z, s); s = __dp4a((int)a4.w, (int)B4.w, s);
                    uint4 a5 = lds128(aA + 80);
                    s = __dp4a((int)a5.x, (int)B5.x, s); s = __dp4a((int)a5.y, (int)B5.y, s);
                    s = __dp4a((int)a5.z, (int)B5.z, s); s = __dp4a((int)a5.w, (int)B5.w, s);
                    uint4 a6 = lds128(aA + 96);
                    s = __dp4a((int)a6.x, (int)B6.x, s); s = __dp4a((int)a6.y, (int)B6.y, s);
                    s = __dp4a((int)a6.z, (int)B6.z, s); s = __dp4a((int)a6.w, (int)B6.w, s);
                    uint4 a7 = lds128(aA + 112);
                    s = __dp4a((int)a7.x, (int)B7.x, s); s = __dp4a((int)a7.y, (int)B7.y, s);
                    s = __dp4a((int)a7.z, (int)B7.z, s); s = __dp4a((int)a7.w, (int)B7.w, s);
                    acc[p] = s;
                }
            }
            size_t base = ((size_t)tile*128 + pxb)*128 + oc;
            #pragma unroll
            for (int p = 0; p < 32; p++)
                g_y[base + (size_t)p*128] = (float)acc[p];
        }
    }
}

// ---------------- launcher ----------------
extern "C" void kernel_launch(void* const* d_in, const int* in_sizes, int n_in,
                              void* d_out, int out_size) {
    const float* x      = (const float*)d_in[0];
    const float* w1     = (const float*)d_in[1];
    const float* w2     = (const float*)d_in[2];
    const float* gamma1 = (const float*)d_in[3];
    const float* beta1  = (const float*)d_in[4];
    const float* gamma2 = (const float*)d_in[5];
    const float* beta2  = (const float*)d_in[6];
    float* out = (float*)d_out;

    static int inited = 0;
    if (!inited) {
        cudaFuncSetAttribute(k_conv, cudaFuncAttributeMaxDynamicSharedMemorySize, SM_SZ);
        inited = 1;
    }

    k_zero<<<2, 256>>>();
    k_alpha<<<dim3(32, 2), 256>>>(w1, w2);
    k_prep<<<4288, 256>>>(w1, w2, x);

    k_conv<<<152, 512, SM_SZ>>>(0);        // 4th launch -> profiled slot
    k_reduce<<<392, 512>>>(0);
    k_stats<<<1, CC>>>(0, gamma1, beta1);

    k_bnq<<<NPX*32/512, 512>>>();
    k_conv<<<152, 512, SM_SZ>>>(1);
    k_reduce<<<392, 512>>>(1);
    k_stats<<<1, CC>>>(1, gamma2, beta2);

    k_final<<<dim3(HH, NB), 256>>>(x, out);
}

// round 10
// speedup vs baseline: 1.3026x; 1.3026x over previous
#include <cuda_runtime.h>
#include <cstdint>

#define CC   128
#define HH   56
#define NB   64
#define HW   3136
#define PW   58
#define PPI  (PW*PW)             // 3364
#define PTOT (NB*PPI)            // 215296
#define NTIL (PTOT/128)          // 1682
#define GUARD 64
#define NPX  (NB*HW)             // 200704

// ---------------- device scratch (zero-init at load; halo/guards never written) ----
__device__ unsigned g_alphaBits[2];
__device__ double   g_red[2][2][CC];
__device__ float    g_coef[2][2][CC];
__device__ __align__(128) signed char g_act8[(size_t)(PTOT + 2*GUARD) * CC]; // NHWC padded, k in 0..15
__device__ __align__(128) signed char g_wp8[2][9 * 128 * 128];               // [tap][oc][ci], m in -7..7
__device__ float    g_y[(size_t)PTOT * CC];                                   // S, NHWC f32 (exact ints)

// ---------------- helpers ----------------
__device__ __forceinline__ uint32_t smem_u32(const void* p) {
    uint32_t a; asm("{ .reg .u64 t; cvta.to.shared.u64 t, %1; cvt.u32.u64 %0, t; }":"=r"(a):"l"(p));
    return a;
}
__device__ __forceinline__ void cp16(uint32_t dst, unsigned long long src) {
    asm volatile("cp.async.cg.shared.global [%0], [%1], 16;"::"r"(dst),"l"(src));
}
#define CP_COMMIT() asm volatile("cp.async.commit_group;":::"memory")
#define CP_WAIT(n)  asm volatile("cp.async.wait_group %0;"::"n"(n):"memory")

__device__ __forceinline__ void mma_s8(int* c, const unsigned* a, unsigned b0, unsigned b1) {
    asm volatile("mma.sync.aligned.m16n8k32.row.col.s32.s8.s8.s32 "
                 "{%0,%1,%2,%3}, {%4,%5,%6,%7}, {%8,%9}, {%0,%1,%2,%3};"
                 : "+r"(c[0]), "+r"(c[1]), "+r"(c[2]), "+r"(c[3])
                 : "r"(a[0]), "r"(a[1]), "r"(a[2]), "r"(a[3]), "r"(b0), "r"(b1));
}
#define LDSM4(r, addr) \
    asm volatile("ldmatrix.sync.aligned.m8n8.x4.shared.b16 {%0,%1,%2,%3}, [%4];" \
                 : "=r"((r)[0]),"=r"((r)[1]),"=r"((r)[2]),"=r"((r)[3]) : "r"(addr))
__device__ __forceinline__ uint4 lds128(uint32_t a) {
    uint4 v;
    asm volatile("ld.shared.v4.u32 {%0,%1,%2,%3}, [%4];"
                 : "=r"(v.x),"=r"(v.y),"=r"(v.z),"=r"(v.w) : "r"(a));
    return v;
}

// ---------------- small kernels (unchanged, known-good) ----------------
__global__ void k_zero() {
    int t = blockIdx.x*blockDim.x + threadIdx.x;
    if (t < 2) g_alphaBits[t] = 0u;
    if (t < 512) ((double*)g_red)[t] = 0.0;
}
__global__ void k_alpha(const float* __restrict__ w1, const float* __restrict__ w2) {
    const float* w = blockIdx.y ? w2 : w1;
    float m = 0.f;
    for (int i = blockIdx.x*blockDim.x + threadIdx.x; i < CC*CC*9; i += gridDim.x*blockDim.x)
        m = fmaxf(m, fabsf(w[i]));
    #pragma unroll
    for (int o = 16; o; o >>= 1) m = fmaxf(m, __shfl_xor_sync(~0u, m, o));
    __shared__ float sm[8];
    if ((threadIdx.x & 31) == 0) sm[threadIdx.x>>5] = m;
    __syncthreads();
    if (threadIdx.x < 32) {
        m = (threadIdx.x < (blockDim.x>>5)) ? sm[threadIdx.x] : 0.f;
        #pragma unroll
        for (int o = 16; o; o >>= 1) m = fmaxf(m, __shfl_xor_sync(~0u, m, o));
        if (threadIdx.x == 0) atomicMax(&g_alphaBits[blockIdx.y], __float_as_uint(m));
    }
}
// fused: blocks [0,1152): weight quant; blocks [1152,4288): activation quant
__global__ void k_prep(const float* __restrict__ w1, const float* __restrict__ w2,
                       const float* __restrict__ x) {
    int b = blockIdx.x, tid = threadIdx.x;
    if (b < 1152) {
        int conv = b / 576;
        const float* w = conv ? w2 : w1;
        float alpha = __uint_as_float(g_alphaBits[conv]);
        int idx = (b % 576)*256 + tid;
        if (idx < 9*128*128) {
            int tap = idx >> 14, rem = idx & 16383, oc = rem >> 7, ci = rem & 127;
            float wc = fminf(fmaxf(w[((size_t)oc*CC + ci)*9 + tap] / alpha, -1.f), 1.f);
            g_wp8[conv][idx] = (signed char)__float2int_rn(wc * 7.f);
        }
        return;
    }
    __shared__ unsigned ws[32*65];
    int bb = b - 1152;
    int n = bb / 49, hw0 = (bb % 49)*64;
    int c4 = tid >> 3, q = tid & 7;
    const float* xp = x + ((size_t)(n*CC + c4*4))*HW + hw0 + q*8;
    unsigned w[8] = {0,0,0,0,0,0,0,0};
    #pragma unroll
    for (int j = 0; j < 4; j++)
        #pragma unroll
        for (int p = 0; p < 8; p++) {
            float v = xp[(size_t)j*HW + p];
            int k = __float2int_rn(fminf(fmaxf(v, 0.f), 1.f) * 15.f);
            w[p] |= (unsigned)k << (8*j);
        }
    #pragma unroll
    for (int p = 0; p < 8; p++) ws[c4*65 + q*8 + p] = w[p];
    __syncthreads();
    unsigned* A = (unsigned*)(g_act8 + (size_t)GUARD*128);
    int wd = tid & 31;
    #pragma unroll
    for (int pl = tid >> 5; pl < 64; pl += 8) {
        int hw = hw0 + pl;
        size_t p = (size_t)n*PPI + (hw/HH + 1)*PW + (hw%HH) + 1;
        A[p*32 + wd] = ws[wd*65 + pl];
    }
}
__global__ void k_bnq() {
    int idx = blockIdx.x*512 + threadIdx.x;
    int v = idx >> 5, q = idx & 31;
    int n = v / HW, hw = v % HW;
    size_t p = (size_t)n*PPI + (hw/HH + 1)*PW + (hw%HH) + 1;
    float4 sv = ((const float4*)(g_y + p*128))[q];
    int c0 = q*4;
    float f[4] = {sv.x, sv.y, sv.z, sv.w};
    unsigned word = 0;
    #pragma unroll
    for (int j = 0; j < 4; j++) {
        float bn = fmaf(g_coef[0][0][c0+j], f[j], g_coef[0][1][c0+j]);
        int k = __float2int_rn(fminf(fmaxf(bn, 0.f), 1.f) * 15.f);
        word |= (unsigned)k << (8*j);
    }
    *(unsigned*)(g_act8 + (size_t)GUARD*128 + p*128 + c0) = word;
}
__global__ void k_reduce(int slot) {
    __shared__ double sm[2][4][128];
    int c = threadIdx.x & 127, g = threadIdx.x >> 7;
    double s = 0.0, s2 = 0.0;
    int base = blockIdx.x*512;
    for (int j = 0; j < 128; j++) {
        int v = base + j*4 + g;
        int n = v / HW, hw = v % HW;
        size_t p = (size_t)n*PPI + (hw/HH + 1)*PW + (hw%HH) + 1;
        double val = (double)g_y[p*128 + c];
        s += val; s2 += val*val;
    }
    sm[0][g][c] = s; sm[1][g][c] = s2;
    __syncthreads();
    if (threadIdx.x < 128) {
        s  = sm[0][0][c]+sm[0][1][c]+sm[0][2][c]+sm[0][3][c];
        s2 = sm[1][0][c]+sm[1][1][c]+sm[1][2][c]+sm[1][3][c];
        atomicAdd(&g_red[slot][0][c], s);
        atomicAdd(&g_red[slot][1][c], s2);
    }
}
__global__ void k_stats(int slot, const float* __restrict__ gamma, const float* __restrict__ beta) {
    int c = threadIdx.x;
    double scale = (double)__uint_as_float(g_alphaBits[slot]) / 105.0;
    double mean = g_red[slot][0][c] / (double)NPX;
    double var  = g_red[slot][1][c] / (double)NPX - mean*mean;
    double rstd = 1.0 / sqrt(var*scale*scale + 1e-5);
    double g = (double)gamma[c];
    g_coef[slot][0][c] = (float)(g * rstd * scale);
    g_coef[slot][1][c] = (float)((double)beta[c] - g * rstd * mean * scale);
}
__global__ void k_final(const float* __restrict__ x, float* __restrict__ out) {
    __shared__ float sf[128*57];
    int y = blockIdx.x + 1, n = blockIdx.y, tid = threadIdx.x;
    size_t p0 = (size_t)n*PPI + y*PW + 1;
    for (int i = tid; i < 56*128; i += 256) {
        int px = i >> 7, c = i & 127;
        sf[c*57 + px] = g_y[(p0 + px)*128 + c];
    }
    __syncthreads();
    for (int i = tid; i < 128*56; i += 256) {
        int c = i / 56, px = i % 56;
        size_t o = ((size_t)(n*CC + c))*HW + (y-1)*HH + px;
        out[o] = fmaf(g_coef[1][0][c], sf[c*57+px], g_coef[1][1][c]) + x[o];
    }
}

// ---------------- hybrid conv v2: double-buffered A, pipelined IMMA, ILP'd dp4a ----
// A: 2 x 246 rows x 144B. B: 9 taps x 128 oc x 128B (chunk-rotated, R5 layout).
#define AROWS 246
#define ASTR  144
#define SM_A0 0
#define SM_A1 (AROWS*ASTR)             // 35424
#define SM_B  (2*AROWS*ASTR)           // 70848
#define SM_SZ (SM_B + 9*128*128)       // 218304

__global__ void __launch_bounds__(512, 1) k_conv(int conv) {
    extern __shared__ __align__(128) char smem[];
    uint32_t sb = smem_u32(smem);
    int tid = threadIdx.x, wid = tid >> 5, lane = tid & 31;

    unsigned long long Ag = (unsigned long long)__cvta_generic_to_global(g_act8 + (size_t)GUARD*128);
    unsigned long long Bg = (unsigned long long)__cvta_generic_to_global(g_wp8[conv]);

    // stage B once (rotated chunks: phys chunk = (c + oc) & 7), 128B rows
    for (int i = tid; i < 9216; i += 512) {
        int tap = i >> 10, r = i & 1023, oc = r >> 3, c = r & 7;
        cp16(sb + SM_B + tap*16384 + oc*128 + (((c + oc) & 7) << 4), Bg + (size_t)i*16);
    }
    // preload A for first tile into buf0
    long long tile0 = blockIdx.x;
    {
        unsigned long long src = Ag + (tile0*128 - 59) * 128;
        for (int i = tid; i < 1968; i += 512)
            cp16(sb + SM_A0 + (i>>3)*ASTR + ((i&7)<<4), src + (size_t)i*16);
    }
    CP_COMMIT();

    const int offs[9] = {-59,-58,-57,-1,0,1,57,58,59};

    // IMMA lane geometry (R5 mapping, verified)
    int lm = lane >> 3, lr = lane & 7;
    uint32_t a_lane = (uint32_t)(((lm & 1)*8 + lr) * ASTR + (lm >> 1)*16);
    int b_oc_loc = (lm >> 1)*8 + lr;
    int b_cad = lm & 1;

    int it = 0;
    for (long long tile = tile0; tile < NTIL; tile += gridDim.x, it++) {
        CP_WAIT(0);                          // my stage(t) done
        __syncthreads();                     // all stage(t) visible; all done compute(t-1)
        uint32_t curA = sb + ((it & 1) ? SM_A1 : SM_A0);
        long long nxt = tile + gridDim.x;
        if (nxt < NTIL) {                    // prefetch next tile into other buf
            uint32_t dst = sb + ((it & 1) ? SM_A0 : SM_A1);
            unsigned long long src = Ag + (nxt*128 - 59) * 128;
            for (int i = tid; i < 1968; i += 512)
                cp16(dst + (i>>3)*ASTR + ((i&7)<<4), src + (size_t)i*16);
            CP_COMMIT();
        }

        if (wid < 8) {
            // ---------------- IMMA half: px 0-63, 36-stage pipelined ----------------
            int mwarp = wid >> 2, nwarp = wid & 3;
            int pxw = mwarp * 32, ocb = nwarp * 32;
            int b_oc = ocb + b_oc_loc;
            uint32_t b_base = sb + SM_B + (uint32_t)b_oc * 128;

            int acc[2][4][4];
            #pragma unroll
            for (int mt = 0; mt < 2; mt++)
                #pragma unroll
                for (int nt = 0; nt < 4; nt++)
                    #pragma unroll
                    for (int j = 0; j < 4; j++) acc[mt][nt][j] = 0;

            unsigned fa0[2][4], fa1[2][4], fb[2][8];
            // prologue: stage 0 (tap 0, ks 0)
            {
                uint32_t aT = curA + (uint32_t)(pxw + offs[0] + 59) * ASTR + a_lane;
                LDSM4(fa0[0], aT);
                LDSM4(fa1[0], aT + 16*ASTR);
                uint32_t rot = (uint32_t)(((b_cad + b_oc) & 7) << 4);
                LDSM4(&fb[0][0], b_base + rot);
                LDSM4(&fb[0][4], b_base + rot + 2048);
            }
            #pragma unroll
            for (int s = 0; s < 36; s++) {
                int cur = s & 1, nx = cur ^ 1;
                if (s < 35) {
                    int s1 = s + 1, tap = s1 >> 2, ks = s1 & 3;
                    uint32_t aT = curA + (uint32_t)(pxw + offs[tap] + 59) * ASTR + a_lane
                                + (uint32_t)ks * 32;
                    LDSM4(fa0[nx], aT);
                    LDSM4(fa1[nx], aT + 16*ASTR);
                    uint32_t bT = b_base + (uint32_t)tap * 16384;
                    uint32_t rot = (uint32_t)(((2*ks + b_cad + b_oc) & 7) << 4);
                    LDSM4(&fb[nx][0], bT + rot);
                    LDSM4(&fb[nx][4], bT + rot + 2048);
                }
                #pragma unroll
                for (int nt = 0; nt < 4; nt++) {
                    mma_s8(acc[0][nt], fa0[cur], fb[cur][nt*2], fb[cur][nt*2+1]);
                    mma_s8(acc[1][nt], fa1[cur], fb[cur][nt*2], fb[cur][nt*2+1]);
                }
            }
            int g = lane >> 2, t = lane & 3;
            #pragma unroll
            for (int mt = 0; mt < 2; mt++) {
                size_t px0 = (size_t)tile*128 + pxw + mt*16 + g;
                #pragma unroll
                for (int nt = 0; nt < 4; nt++) {
                    int oc = ocb + nt*8 + 2*t;
                    *(float2*)(g_y + px0*128 + oc) =
                        make_float2((float)acc[mt][nt][0], (float)acc[mt][nt][1]);
                    *(float2*)(g_y + (px0 + 8)*128 + oc) =
                        make_float2((float)acc[mt][nt][2], (float)acc[mt][nt][3]);
                }
            }
        } else {
            // ---------------- dp4a half: px 64-127, 4 chains per px-pair ----------------
            int sub = wid - 8;
            int ocb = (sub & 3) * 32, pxb = 64 + (sub >> 2) * 32;
            int oc = ocb + lane;
            int acc[32];
            #pragma unroll
            for (int p = 0; p < 32; p++) acc[p] = 0;

            #pragma unroll 1
            for (int tap = 0; tap < 9; tap++) {
                int off = (tap/3 - 1)*PW + (tap%3 - 1);
                uint32_t bRow = sb + SM_B + (uint32_t)(tap*128 + oc)*128;
                uint4 B0 = lds128(bRow + (((0 + oc) & 7) << 4));
                uint4 B1 = lds128(bRow + (((1 + oc) & 7) << 4));
                uint4 B2 = lds128(bRow + (((2 + oc) & 7) << 4));
                uint4 B3 = lds128(bRow + (((3 + oc) & 7) << 4));
                uint4 B4 = lds128(bRow + (((4 + oc) & 7) << 4));
                uint4 B5 = lds128(bRow + (((5 + oc) & 7) << 4));
                uint4 B6 = lds128(bRow + (((6 + oc) & 7) << 4));
                uint4 B7 = lds128(bRow + (((7 + oc) & 7) << 4));
                uint32_t aBase = curA + (uint32_t)(pxb + off + 59) * ASTR;
                #pragma unroll 4
                for (int pp = 0; pp < 16; pp++) {
                    uint32_t aA = aBase + (2*pp)*ASTR;
                    // px0: two chains
                    uint4 a0 = lds128(aA),      a1 = lds128(aA + 16);
                    uint4 a2 = lds128(aA + 32), a3 = lds128(aA + 48);
                    uint4 a4 = lds128(aA + 64), a5 = lds128(aA + 80);
                    uint4 a6 = lds128(aA + 96), a7 = lds128(aA + 112);
                    int s = acc[2*pp];
                    s = __dp4a((int)a0.x,(int)B0.x,s); s = __dp4a((int)a0.y,(int)B0.y,s);
                    s = __dp4a((int)a0.z,(int)B0.z,s); s = __dp4a((int)a0.w,(int)B0.w,s);
                    s = __dp4a((int)a1.x,(int)B1.x,s); s = __dp4a((int)a1.y,(int)B1.y,s);
                    s = __dp4a((int)a1.z,(int)B1.z,s); s = __dp4a((int)a1.w,(int)B1.w,s);
                    s = __dp4a((int)a2.x,(int)B2.x,s); s = __dp4a((int)a2.y,(int)B2.y,s);
                    s = __dp4a((int)a2.z,(int)B2.z,s); s = __dp4a((int)a2.w,(int)B2.w,s);
                    s = __dp4a((int)a3.x,(int)B3.x,s); s = __dp4a((int)a3.y,(int)B3.y,s);
                    s = __dp4a((int)a3.z,(int)B3.z,s); s = __dp4a((int)a3.w,(int)B3.w,s);
                    int u = __dp4a((int)a4.x,(int)B4.x,0); u = __dp4a((int)a4.y,(int)B4.y,u);
                    u = __dp4a((int)a4.z,(int)B4.z,u); u = __dp4a((int)a4.w,(int)B4.w,u);
                    u = __dp4a((int)a5.x,(int)B5.x,u); u = __dp4a((int)a5.y,(int)B5.y,u);
                    u = __dp4a((int)a5.z,(int)B5.z,u); u = __dp4a((int)a5.w,(int)B5.w,u);
                    u = __dp4a((int)a6.x,(int)B6.x,u); u = __dp4a((int)a6.y,(int)B6.y,u);
                    u = __dp4a((int)a6.z,(int)B6.z,u); u = __dp4a((int)a6.w,(int)B6.w,u);
                    u = __dp4a((int)a7.x,(int)B7.x,u); u = __dp4a((int)a7.y,(int)B7.y,u);
                    u = __dp4a((int)a7.z,(int)B7.z,u); u = __dp4a((int)a7.w,(int)B7.w,u);
                    acc[2*pp] = s + u;
                    // px1: two chains
                    uint32_t aB = aA + ASTR;
                    uint4 c0 = lds128(aB),      c1 = lds128(aB + 16);
                    uint4 c2 = lds128(aB + 32), c3 = lds128(aB + 48);
                    uint4 c4 = lds128(aB + 64), c5 = lds128(aB + 80);
                    uint4 c6 = lds128(aB + 96), c7 = lds128(aB + 112);
                    int v = acc[2*pp+1];
                    v = __dp4a((int)c0.x,(int)B0.x,v); v = __dp4a((int)c0.y,(int)B0.y,v);
                    v = __dp4a((int)c0.z,(int)B0.z,v); v = __dp4a((int)c0.w,(int)B0.w,v);
                    v = __dp4a((int)c1.x,(int)B1.x,v); v = __dp4a((int)c1.y,(int)B1.y,v);
                    v = __dp4a((int)c1.z,(int)B1.z,v); v = __dp4a((int)c1.w,(int)B1.w,v);
                    v = __dp4a((int)c2.x,(int)B2.x,v); v = __dp4a((int)c2.y,(int)B2.y,v);
                    v = __dp4a((int)c2.z,(int)B2.z,v); v = __dp4a((int)c2.w,(int)B2.w,v);
                    v = __dp4a((int)c3.x,(int)B3.x,v); v = __dp4a((int)c3.y,(int)B3.y,v);
                    v = __dp4a((int)c3.z,(int)B3.z,v); v = __dp4a((int)c3.w,(int)B3.w,v);
                    int wv = __dp4a((int)c4.x,(int)B4.x,0); wv = __dp4a((int)c4.y,(int)B4.y,wv);
                    wv = __dp4a((int)c4.z,(int)B4.z,wv); wv = __dp4a((int)c4.w,(int)B4.w,wv);
                    wv = __dp4a((int)c5.x,(int)B5.x,wv); wv = __dp4a((int)c5.y,(int)B5.y,wv);
                    wv = __dp4a((int)c5.z,(int)B5.z,wv); wv = __dp4a((int)c5.w,(int)B5.w,wv);
                    wv = __dp4a((int)c6.x,(int)B6.x,wv); wv = __dp4a((int)c6.y,(int)B6.y,wv);
                    wv = __dp4a((int)c6.z,(int)B6.z,wv); wv = __dp4a((int)c6.w,(int)B6.w,wv);
                    wv = __dp4a((int)c7.x,(int)B7.x,wv); wv = __dp4a((int)c7.y,(int)B7.y,wv);
                    wv = __dp4a((int)c7.z,(int)B7.z,wv); wv = __dp4a((int)c7.w,(int)B7.w,wv);
                    acc[2*pp+1] = v + wv;
                }
            }
            size_t base = ((size_t)tile*128 + pxb)*128 + oc;
            #pragma unroll
            for (int p = 0; p < 32; p++)
                g_y[base + (size_t)p*128] = (float)acc[p];
        }
    }
}

// ---------------- launcher ----------------
extern "C" void kernel_launch(void* const* d_in, const int* in_sizes, int n_in,
                              void* d_out, int out_size) {
    const float* x      = (const float*)d_in[0];
    const float* w1     = (const float*)d_in[1];
    const float* w2     = (const float*)d_in[2];
    const float* gamma1 = (const float*)d_in[3];
    const float* beta1  = (const float*)d_in[4];
    const float* gamma2 = (const float*)d_in[5];
    const float* beta2  = (const float*)d_in[6];
    float* out = (float*)d_out;

    static int inited = 0;
    if (!inited) {
        cudaFuncSetAttribute(k_conv, cudaFuncAttributeMaxDynamicSharedMemorySize, SM_SZ);
        inited = 1;
    }

    k_zero<<<2, 256>>>();
    k_alpha<<<dim3(32, 2), 256>>>(w1, w2);
    k_prep<<<4288, 256>>>(w1, w2, x);

    k_conv<<<152, 512, SM_SZ>>>(0);        // 4th launch -> profiled slot
    k_reduce<<<392, 512>>>(0);
    k_stats<<<1, CC>>>(0, gamma1, beta1);

    k_bnq<<<NPX*32/512, 512>>>();
    k_conv<<<152, 512, SM_SZ>>>(1);
    k_reduce<<<392, 512>>>(1);
    k_stats<<<1, CC>>>(1, gamma2, beta2);

    k_final<<<dim3(HH, NB), 256>>>(x, out);
}

// round 11
// speedup vs baseline: 1.4843x; 1.1395x over previous
#include <cuda_runtime.h>
#include <cstdint>

#define CC   128
#define HH   56
#define NB   64
#define HW   3136
#define PW   58
#define PPI  (PW*PW)             // 3364
#define PTOT (NB*PPI)            // 215296
#define NTIL (PTOT/128)          // 1682
#define GUARD 64
#define NPX  (NB*HW)             // 200704

// ---------------- device scratch (zero-init at load; halo/guards never written) ----
__device__ unsigned g_alphaBits[2];
__device__ double   g_red[2][2][CC];
__device__ float    g_coef[2][2][CC];
__device__ __align__(128) signed char g_act8[(size_t)(PTOT + 2*GUARD) * CC]; // NHWC padded, k in 0..15
__device__ __align__(128) signed char g_wp8[2][9 * 128 * 128];               // [tap][oc][ci], m in -7..7
__device__ float    g_y[(size_t)PTOT * CC];                                   // S, NHWC f32 (exact ints)

// ---------------- helpers ----------------
__device__ __forceinline__ uint32_t smem_u32(const void* p) {
    uint32_t a; asm("{ .reg .u64 t; cvta.to.shared.u64 t, %1; cvt.u32.u64 %0, t; }":"=r"(a):"l"(p));
    return a;
}
__device__ __forceinline__ void cp16(uint32_t dst, unsigned long long src) {
    asm volatile("cp.async.cg.shared.global [%0], [%1], 16;"::"r"(dst),"l"(src));
}
#define CP_COMMIT() asm volatile("cp.async.commit_group;":::"memory")
#define CP_WAIT(n)  asm volatile("cp.async.wait_group %0;"::"n"(n):"memory")

__device__ __forceinline__ void mma_s8(int* c, const unsigned* a, unsigned b0, unsigned b1) {
    asm volatile("mma.sync.aligned.m16n8k32.row.col.s32.s8.s8.s32 "
                 "{%0,%1,%2,%3}, {%4,%5,%6,%7}, {%8,%9}, {%0,%1,%2,%3};"
                 : "+r"(c[0]), "+r"(c[1]), "+r"(c[2]), "+r"(c[3])
                 : "r"(a[0]), "r"(a[1]), "r"(a[2]), "r"(a[3]), "r"(b0), "r"(b1));
}
#define LDSM4(r, addr) \
    asm volatile("ldmatrix.sync.aligned.m8n8.x4.shared.b16 {%0,%1,%2,%3}, [%4];" \
                 : "=r"((r)[0]),"=r"((r)[1]),"=r"((r)[2]),"=r"((r)[3]) : "r"(addr))
__device__ __forceinline__ uint4 lds128(uint32_t a) {
    uint4 v;
    asm volatile("ld.shared.v4.u32 {%0,%1,%2,%3}, [%4];"
                 : "=r"(v.x),"=r"(v.y),"=r"(v.z),"=r"(v.w) : "r"(a));
    return v;
}
__device__ __forceinline__ int dp4x4(uint4 a, uint4 b, int s) {
    s = __dp4a((int)a.x,(int)b.x,s); s = __dp4a((int)a.y,(int)b.y,s);
    s = __dp4a((int)a.z,(int)b.z,s); s = __dp4a((int)a.w,(int)b.w,s);
    return s;
}

// ---------------- small kernels (unchanged, known-good) ----------------
__global__ void k_zero() {
    int t = blockIdx.x*blockDim.x + threadIdx.x;
    if (t < 2) g_alphaBits[t] = 0u;
    if (t < 512) ((double*)g_red)[t] = 0.0;
}
__global__ void k_alpha(const float* __restrict__ w1, const float* __restrict__ w2) {
    const float* w = blockIdx.y ? w2 : w1;
    float m = 0.f;
    for (int i = blockIdx.x*blockDim.x + threadIdx.x; i < CC*CC*9; i += gridDim.x*blockDim.x)
        m = fmaxf(m, fabsf(w[i]));
    #pragma unroll
    for (int o = 16; o; o >>= 1) m = fmaxf(m, __shfl_xor_sync(~0u, m, o));
    __shared__ float sm[8];
    if ((threadIdx.x & 31) == 0) sm[threadIdx.x>>5] = m;
    __syncthreads();
    if (threadIdx.x < 32) {
        m = (threadIdx.x < (blockDim.x>>5)) ? sm[threadIdx.x] : 0.f;
        #pragma unroll
        for (int o = 16; o; o >>= 1) m = fmaxf(m, __shfl_xor_sync(~0u, m, o));
        if (threadIdx.x == 0) atomicMax(&g_alphaBits[blockIdx.y], __float_as_uint(m));
    }
}
__global__ void k_prep(const float* __restrict__ w1, const float* __restrict__ w2,
                       const float* __restrict__ x) {
    int b = blockIdx.x, tid = threadIdx.x;
    if (b < 1152) {
        int conv = b / 576;
        const float* w = conv ? w2 : w1;
        float alpha = __uint_as_float(g_alphaBits[conv]);
        int idx = (b % 576)*256 + tid;
        if (idx < 9*128*128) {
            int tap = idx >> 14, rem = idx & 16383, oc = rem >> 7, ci = rem & 127;
            float wc = fminf(fmaxf(w[((size_t)oc*CC + ci)*9 + tap] / alpha, -1.f), 1.f);
            g_wp8[conv][idx] = (signed char)__float2int_rn(wc * 7.f);
        }
        return;
    }
    __shared__ unsigned ws[32*65];
    int bb = b - 1152;
    int n = bb / 49, hw0 = (bb % 49)*64;
    int c4 = tid >> 3, q = tid & 7;
    const float* xp = x + ((size_t)(n*CC + c4*4))*HW + hw0 + q*8;
    unsigned w[8] = {0,0,0,0,0,0,0,0};
    #pragma unroll
    for (int j = 0; j < 4; j++)
        #pragma unroll
        for (int p = 0; p < 8; p++) {
            float v = xp[(size_t)j*HW + p];
            int k = __float2int_rn(fminf(fmaxf(v, 0.f), 1.f) * 15.f);
            w[p] |= (unsigned)k << (8*j);
        }
    #pragma unroll
    for (int p = 0; p < 8; p++) ws[c4*65 + q*8 + p] = w[p];
    __syncthreads();
    unsigned* A = (unsigned*)(g_act8 + (size_t)GUARD*128);
    int wd = tid & 31;
    #pragma unroll
    for (int pl = tid >> 5; pl < 64; pl += 8) {
        int hw = hw0 + pl;
        size_t p = (size_t)n*PPI + (hw/HH + 1)*PW + (hw%HH) + 1;
        A[p*32 + wd] = ws[wd*65 + pl];
    }
}
__global__ void k_bnq() {
    int idx = blockIdx.x*512 + threadIdx.x;
    int v = idx >> 5, q = idx & 31;
    int n = v / HW, hw = v % HW;
    size_t p = (size_t)n*PPI + (hw/HH + 1)*PW + (hw%HH) + 1;
    float4 sv = ((const float4*)(g_y + p*128))[q];
    int c0 = q*4;
    float f[4] = {sv.x, sv.y, sv.z, sv.w};
    unsigned word = 0;
    #pragma unroll
    for (int j = 0; j < 4; j++) {
        float bn = fmaf(g_coef[0][0][c0+j], f[j], g_coef[0][1][c0+j]);
        int k = __float2int_rn(fminf(fmaxf(bn, 0.f), 1.f) * 15.f);
        word |= (unsigned)k << (8*j);
    }
    *(unsigned*)(g_act8 + (size_t)GUARD*128 + p*128 + c0) = word;
}
__global__ void k_reduce(int slot) {
    __shared__ double sm[2][4][128];
    int c = threadIdx.x & 127, g = threadIdx.x >> 7;
    double s = 0.0, s2 = 0.0;
    int base = blockIdx.x*512;
    for (int j = 0; j < 128; j++) {
        int v = base + j*4 + g;
        int n = v / HW, hw = v % HW;
        size_t p = (size_t)n*PPI + (hw/HH + 1)*PW + (hw%HH) + 1;
        double val = (double)g_y[p*128 + c];
        s += val; s2 += val*val;
    }
    sm[0][g][c] = s; sm[1][g][c] = s2;
    __syncthreads();
    if (threadIdx.x < 128) {
        s  = sm[0][0][c]+sm[0][1][c]+sm[0][2][c]+sm[0][3][c];
        s2 = sm[1][0][c]+sm[1][1][c]+sm[1][2][c]+sm[1][3][c];
        atomicAdd(&g_red[slot][0][c], s);
        atomicAdd(&g_red[slot][1][c], s2);
    }
}
__global__ void k_stats(int slot, const float* __restrict__ gamma, const float* __restrict__ beta) {
    int c = threadIdx.x;
    double scale = (double)__uint_as_float(g_alphaBits[slot]) / 105.0;
    double mean = g_red[slot][0][c] / (double)NPX;
    double var  = g_red[slot][1][c] / (double)NPX - mean*mean;
    double rstd = 1.0 / sqrt(var*scale*scale + 1e-5);
    double g = (double)gamma[c];
    g_coef[slot][0][c] = (float)(g * rstd * scale);
    g_coef[slot][1][c] = (float)((double)beta[c] - g * rstd * mean * scale);
}
__global__ void k_final(const float* __restrict__ x, float* __restrict__ out) {
    __shared__ float sf[128*57];
    int y = blockIdx.x + 1, n = blockIdx.y, tid = threadIdx.x;
    size_t p0 = (size_t)n*PPI + y*PW + 1;
    for (int i = tid; i < 56*128; i += 256) {
        int px = i >> 7, c = i & 127;
        sf[c*57 + px] = g_y[(p0 + px)*128 + c];
    }
    __syncthreads();
    for (int i = tid; i < 128*56; i += 256) {
        int c = i / 56, px = i % 56;
        size_t o = ((size_t)(n*CC + c))*HW + (y-1)*HH + px;
        out[o] = fmaf(g_coef[1][0][c], sf[c*57+px], g_coef[1][1][c]) + x[o];
    }
}

// ---------------- hybrid conv v3: fused-tap dp4a (A reads /3), pipelined IMMA ----
#define AROWS 246
#define ASTR  144
#define SM_A0 0
#define SM_A1 (AROWS*ASTR)             // 35424
#define SM_B  (2*AROWS*ASTR)           // 70848
#define SM_SZ (SM_B + 9*128*128)       // 218304

__global__ void __launch_bounds__(512, 1) k_conv(int conv) {
    extern __shared__ __align__(128) char smem[];
    uint32_t sb = smem_u32(smem);
    int tid = threadIdx.x, wid = tid >> 5, lane = tid & 31;

    unsigned long long Ag = (unsigned long long)__cvta_generic_to_global(g_act8 + (size_t)GUARD*128);
    unsigned long long Bg = (unsigned long long)__cvta_generic_to_global(g_wp8[conv]);

    // stage B once (rotated chunks: phys chunk = (c + oc) & 7), 128B rows
    for (int i = tid; i < 9216; i += 512) {
        int tap = i >> 10, r = i & 1023, oc = r >> 3, c = r & 7;
        cp16(sb + SM_B + tap*16384 + oc*128 + (((c + oc) & 7) << 4), Bg + (size_t)i*16);
    }
    // preload A for first tile into buf0
    long long tile0 = blockIdx.x;
    {
        unsigned long long src = Ag + (tile0*128 - 59) * 128;
        for (int i = tid; i < 1968; i += 512)
            cp16(sb + SM_A0 + (i>>3)*ASTR + ((i&7)<<4), src + (size_t)i*16);
    }
    CP_COMMIT();

    const int offs[9] = {-59,-58,-57,-1,0,1,57,58,59};

    // IMMA lane geometry (verified)
    int lm = lane >> 3, lr = lane & 7;
    uint32_t a_lane = (uint32_t)(((lm & 1)*8 + lr) * ASTR + (lm >> 1)*16);
    int b_oc_loc = (lm >> 1)*8 + lr;
    int b_cad = lm & 1;

    int it = 0;
    for (long long tile = tile0; tile < NTIL; tile += gridDim.x, it++) {
        CP_WAIT(0);
        __syncthreads();
        uint32_t curA = sb + ((it & 1) ? SM_A1 : SM_A0);
        long long nxt = tile + gridDim.x;
        if (nxt < NTIL) {
            uint32_t dst = sb + ((it & 1) ? SM_A0 : SM_A1);
            unsigned long long src = Ag + (nxt*128 - 59) * 128;
            for (int i = tid; i < 1968; i += 512)
                cp16(dst + (i>>3)*ASTR + ((i&7)<<4), src + (size_t)i*16);
            CP_COMMIT();
        }

        if (wid < 8) {
            // ---------------- IMMA half: px 0-63, 36-stage pipelined (unchanged) ----
            int mwarp = wid >> 2, nwarp = wid & 3;
            int pxw = mwarp * 32, ocb = nwarp * 32;
            int b_oc = ocb + b_oc_loc;
            uint32_t b_base = sb + SM_B + (uint32_t)b_oc * 128;

            int acc[2][4][4];
            #pragma unroll
            for (int mt = 0; mt < 2; mt++)
                #pragma unroll
                for (int nt = 0; nt < 4; nt++)
                    #pragma unroll
                    for (int j = 0; j < 4; j++) acc[mt][nt][j] = 0;

            unsigned fa0[2][4], fa1[2][4], fb[2][8];
            {
                uint32_t aT = curA + (uint32_t)(pxw + offs[0] + 59) * ASTR + a_lane;
                LDSM4(fa0[0], aT);
                LDSM4(fa1[0], aT + 16*ASTR);
                uint32_t rot = (uint32_t)(((b_cad + b_oc) & 7) << 4);
                LDSM4(&fb[0][0], b_base + rot);
                LDSM4(&fb[0][4], b_base + rot + 2048);
            }
            #pragma unroll
            for (int s = 0; s < 36; s++) {
                int cur = s & 1, nx = cur ^ 1;
                if (s < 35) {
                    int s1 = s + 1, tap = s1 >> 2, ks = s1 & 3;
                    uint32_t aT = curA + (uint32_t)(pxw + offs[tap] + 59) * ASTR + a_lane
                                + (uint32_t)ks * 32;
                    LDSM4(fa0[nx], aT);
                    LDSM4(fa1[nx], aT + 16*ASTR);
                    uint32_t bT = b_base + (uint32_t)tap * 16384;
                    uint32_t rot = (uint32_t)(((2*ks + b_cad + b_oc) & 7) << 4);
                    LDSM4(&fb[nx][0], bT + rot);
                    LDSM4(&fb[nx][4], bT + rot + 2048);
                }
                #pragma unroll
                for (int nt = 0; nt < 4; nt++) {
                    mma_s8(acc[0][nt], fa0[cur], fb[cur][nt*2], fb[cur][nt*2+1]);
                    mma_s8(acc[1][nt], fa1[cur], fb[cur][nt*2], fb[cur][nt*2+1]);
                }
            }
            int g = lane >> 2, t = lane & 3;
            #pragma unroll
            for (int mt = 0; mt < 2; mt++) {
                size_t px0 = (size_t)tile*128 + pxw + mt*16 + g;
                #pragma unroll
                for (int nt = 0; nt < 4; nt++) {
                    int oc = ocb + nt*8 + 2*t;
                    *(float2*)(g_y + px0*128 + oc) =
                        make_float2((float)acc[mt][nt][0], (float)acc[mt][nt][1]);
                    *(float2*)(g_y + (px0 + 8)*128 + oc) =
                        make_float2((float)acc[mt][nt][2], (float)acc[mt][nt][3]);
                }
            }
        } else {
            // -------- dp4a half: px 64-127, horizontal-tap-fused A sweep --------
            int sub = wid - 8;
            int ocb = (sub & 3) * 32, pxb = 64 + (sub >> 2) * 32;
            int oc = ocb + lane;
            int acc[32];
            #pragma unroll
            for (int p = 0; p < 32; p++) acc[p] = 0;

            #pragma unroll 1
            for (int hr = 0; hr < 6; hr++) {      // hr = h*3 + r
                int h = (hr >= 3), r = hr - 3*(hr >= 3);
                // B for taps 3r,3r+1,3r+2, ci half h (logical chunks 4h..4h+3)
                uint4 Bc[3][4];
                #pragma unroll
                for (int ci = 0; ci < 3; ci++) {
                    uint32_t bRow = sb + SM_B + (uint32_t)((3*r + ci)*128 + oc)*128;
                    #pragma unroll
                    for (int j = 0; j < 4; j++)
                        Bc[ci][j] = lds128(bRow + ((((4*h + j) + oc) & 7) << 4));
                }
                // A sweep: A px = pxb + (r-1)*PW + (q-1), q = 0..33
                uint32_t abase = curA + (uint32_t)(pxb + (r-1)*PW - 1 + 59)*ASTR + (uint32_t)h*64;
                #pragma unroll
                for (int q = 0; q < 34; q++) {
                    uint32_t aA = abase + (uint32_t)q*ASTR;
                    uint4 A0 = lds128(aA), A1 = lds128(aA + 16),
                          A2 = lds128(aA + 32), A3 = lds128(aA + 48);
                    if (q <= 31) {                 // c=-1 -> out q, tap 3r+0
                        int s = acc[q];
                        s = dp4x4(A0, Bc[0][0], s); s = dp4x4(A1, Bc[0][1], s);
                        s = dp4x4(A2, Bc[0][2], s); s = dp4x4(A3, Bc[0][3], s);
                        acc[q] = s;
                    }
                    if (q >= 1 && q <= 32) {       // c=0 -> out q-1, tap 3r+1
                        int s = acc[q-1];
                        s = dp4x4(A0, Bc[1][0], s); s = dp4x4(A1, Bc[1][1], s);
                        s = dp4x4(A2, Bc[1][2], s); s = dp4x4(A3, Bc[1][3], s);
                        acc[q-1] = s;
                    }
                    if (q >= 2) {                  // c=+1 -> out q-2, tap 3r+2
                        int s = acc[q-2];
                        s = dp4x4(A0, Bc[2][0], s); s = dp4x4(A1, Bc[2][1], s);
                        s = dp4x4(A2, Bc[2][2], s); s = dp4x4(A3, Bc[2][3], s);
                        acc[q-2] = s;
                    }
                }
            }
            size_t base = ((size_t)tile*128 + pxb)*128 + oc;
            #pragma unroll
            for (int p = 0; p < 32; p++)
                g_y[base + (size_t)p*128] = (float)acc[p];
        }
    }
}

// ---------------- launcher ----------------
extern "C" void kernel_launch(void* const* d_in, const int* in_sizes, int n_in,
                              void* d_out, int out_size) {
    const float* x      = (const float*)d_in[0];
    const float* w1     = (const float*)d_in[1];
    const float* w2     = (const float*)d_in[2];
    const float* gamma1 = (const float*)d_in[3];
    const float* beta1  = (const float*)d_in[4];
    const float* gamma2 = (const float*)d_in[5];
    const float* beta2  = (const float*)d_in[6];
    float* out = (float*)d_out;

    static int inited = 0;
    if (!inited) {
        cudaFuncSetAttribute(k_conv, cudaFuncAttributeMaxDynamicSharedMemorySize, SM_SZ);
        inited = 1;
    }

    k_zero<<<2, 256>>>();
    k_alpha<<<dim3(32, 2), 256>>>(w1, w2);
    k_prep<<<4288, 256>>>(w1, w2, x);

    k_conv<<<152, 512, SM_SZ>>>(0);        // 4th launch -> profiled slot
    k_reduce<<<392, 512>>>(0);
    k_stats<<<1, CC>>>(0, gamma1, beta1);

    k_bnq<<<NPX*32/512, 512>>>();
    k_conv<<<152, 512, SM_SZ>>>(1);
    k_reduce<<<392, 512>>>(1);
    k_stats<<<1, CC>>>(1, gamma2, beta2);

    k_final<<<dim3(HH, NB), 256>>>(x, out);
}